// round 7
// baseline (speedup 1.0000x reference)
#include <cuda_runtime.h>

#define THRESH 0.5f
#define ALPHA  0.1f

// B=64, N=16384, C=16 -> 1,048,576 rows = 4,194,304 float4 slots.
// 4 lanes per row (one float4 each): every warp LDG.128 covers 512
// contiguous bytes. Unroll x4 -> 8 independent LDG.128 in flight per
// thread (front-batched), __ldcs evict-first since data is read once.

static constexpr int THREADS = 256;
static constexpr int BLOCKS = 1184;     // 148 SMs * 8

__device__ float g_partials[BLOCKS];
__device__ unsigned int g_done = 0;     // self-resetting last-block ticket

__device__ __forceinline__ float4 ldcs4(const float4* p) {
    return __ldcs(p);
}

__device__ __forceinline__ float contrib(float4 xv, float4 yv, int q) {
    // broadcast y[row,0] (held by lane q==0 of the 4-lane group)
    const float y0 = __shfl_sync(0xFFFFFFFFu, yv.x, 0, 4);
    float d0 = yv.x - xv.x;
    float d1 = yv.y - xv.y;
    float d2 = yv.z - xv.z;
    float d3 = yv.w - xv.w;
    float sq = d0 * d0 + d1 * d1 + d2 * d2 + d3 * d3;
    if (y0 > THRESH) return sq;
    return (q == 0) ? (ALPHA * xv.x * xv.x) : 0.0f;
}

__global__ __launch_bounds__(THREADS) void mloss_kernel(
    const float* __restrict__ x,
    const float* __restrict__ y,
    float* __restrict__ out,
    int n_slots)
{
    const int g0 = blockIdx.x * THREADS + threadIdx.x;
    const int stride = gridDim.x * THREADS;
    const int q = threadIdx.x & 3;       // loop-invariant (stride % 4 == 0)

    const float4* xp = reinterpret_cast<const float4*>(x);
    const float4* yp = reinterpret_cast<const float4*>(y);

    float acc = 0.0f;

    int slot = g0;
    // main: 4 slots per iteration -> 8 independent 16B loads in flight
    for (; slot + 3 * stride < n_slots; slot += 4 * stride) {
        const int s0 = slot;
        const int s1 = slot + stride;
        const int s2 = slot + 2 * stride;
        const int s3 = slot + 3 * stride;

        float4 xv0 = ldcs4(xp + s0), yv0 = ldcs4(yp + s0);
        float4 xv1 = ldcs4(xp + s1), yv1 = ldcs4(yp + s1);
        float4 xv2 = ldcs4(xp + s2), yv2 = ldcs4(yp + s2);
        float4 xv3 = ldcs4(xp + s3), yv3 = ldcs4(yp + s3);

        acc += contrib(xv0, yv0, q);
        acc += contrib(xv1, yv1, q);
        acc += contrib(xv2, yv2, q);
        acc += contrib(xv3, yv3, q);
    }
    // tail
    for (; slot < n_slots; slot += stride) {
        acc += contrib(ldcs4(xp + slot), ldcs4(yp + slot), q);
    }

    // ---- block reduction ----
    #pragma unroll
    for (int off = 16; off > 0; off >>= 1)
        acc += __shfl_xor_sync(0xFFFFFFFFu, acc, off);

    __shared__ float warp_sums[THREADS / 32];
    __shared__ bool is_last;
    const int lane = threadIdx.x & 31;
    const int wid  = threadIdx.x >> 5;
    if (lane == 0) warp_sums[wid] = acc;
    __syncthreads();

    if (wid == 0) {
        float v = (lane < THREADS / 32) ? warp_sums[lane] : 0.0f;
        #pragma unroll
        for (int off = 4; off > 0; off >>= 1)
            v += __shfl_xor_sync(0xFFFFFFFFu, v, off);
        if (lane == 0) {
            g_partials[blockIdx.x] = v;
            __threadfence();
            unsigned int t = atomicAdd(&g_done, 1u);
            is_last = (t == (unsigned int)gridDim.x - 1u);
        }
    }
    __syncthreads();

    // ---- last block reduces the 1184 partials and stores the scalar ----
    if (is_last) {
        float v = 0.0f;
        for (int i = threadIdx.x; i < gridDim.x; i += THREADS)
            v += g_partials[i];
        #pragma unroll
        for (int off = 16; off > 0; off >>= 1)
            v += __shfl_xor_sync(0xFFFFFFFFu, v, off);
        __syncthreads();                  // warp_sums reuse
        if (lane == 0) warp_sums[wid] = v;
        __syncthreads();
        if (wid == 0) {
            float t = (lane < THREADS / 32) ? warp_sums[lane] : 0.0f;
            #pragma unroll
            for (int off = 4; off > 0; off >>= 1)
                t += __shfl_xor_sync(0xFFFFFFFFu, t, off);
            if (lane == 0) {
                out[0] = t;
                g_done = 0;               // reset for next graph replay
            }
        }
    }
}

extern "C" void kernel_launch(void* const* d_in, const int* in_sizes, int n_in,
                              void* d_out, int out_size) {
    const float* x = (const float*)d_in[0];
    const float* y = (const float*)d_in[1];
    float* out = (float*)d_out;

    const int total = in_sizes[0];    // B*N*C = 16,777,216
    const int n_slots = total / 4;    // one float4 per slot

    mloss_kernel<<<BLOCKS, THREADS>>>(x, y, out, n_slots);
}

// round 8
// speedup vs baseline: 1.0096x; 1.0096x over previous
#include <cuda_runtime.h>

#define THRESH 0.5f
#define ALPHA  0.1f

// B=64, N=16384, C=16 -> 1,048,576 rows of 16 fp32 = 4,194,304 float4 slots.
// 4 lanes cooperate on one row (one float4 each): every warp-level LDG.128
// covers 512 fully-contiguous bytes. R3-proven optimum: 2-slot unroll,
// 2 shfl_xor row-reduce, 30 regs, occ 99%. Fused last-block finish
// (R4/R7-proven) removes the separate init launch.

static constexpr int C = 16;
static constexpr int THREADS = 256;
static constexpr int BLOCKS = 1184;     // 148 SMs * 8 blocks

__device__ float g_partials[BLOCKS];
__device__ unsigned int g_done = 0;     // self-resetting last-block ticket

__device__ __forceinline__ float slot_contrib(
    const float* __restrict__ x, const float* __restrict__ y, int slot)
{
    const int row = slot >> 2;
    const int q = slot & 3;
    const int base = row * C + q * 4;

    const float4 xv = *reinterpret_cast<const float4*>(x + base);
    const float4 yv = *reinterpret_cast<const float4*>(y + base);

    float d0 = yv.x - xv.x;
    float d1 = yv.y - xv.y;
    float d2 = yv.z - xv.z;
    float d3 = yv.w - xv.w;
    float sq = d0 * d0 + d1 * d1 + d2 * d2 + d3 * d3;

    // sum the 4 quarter-partials across the 4-lane group
    sq += __shfl_xor_sync(0xFFFFFFFFu, sq, 1);
    sq += __shfl_xor_sync(0xFFFFFFFFu, sq, 2);

    // lane with q==0 holds x[...,0] (xv.x) and y[...,0] (yv.x)
    if (q == 0) {
        return (yv.x > THRESH) ? sq : (ALPHA * xv.x * xv.x);
    }
    return 0.0f;
}

__global__ __launch_bounds__(THREADS) void mloss_kernel(
    const float* __restrict__ x,
    const float* __restrict__ y,
    float* __restrict__ out,
    int n_slots)
{
    const int g0 = blockIdx.x * THREADS + threadIdx.x;
    const int stride = gridDim.x * THREADS;

    float acc = 0.0f;

    // 2-slot unroll: 4 independent LDG.128 in flight per thread (R3 optimum)
    int slot = g0;
    for (; slot + stride < n_slots; slot += 2 * stride) {
        acc += slot_contrib(x, y, slot);
        acc += slot_contrib(x, y, slot + stride);
    }
    if (slot < n_slots) {
        acc += slot_contrib(x, y, slot);
    }

    // ---- block reduction ----
    #pragma unroll
    for (int off = 16; off > 0; off >>= 1)
        acc += __shfl_xor_sync(0xFFFFFFFFu, acc, off);

    __shared__ float warp_sums[THREADS / 32];
    __shared__ bool is_last;
    const int lane = threadIdx.x & 31;
    const int wid  = threadIdx.x >> 5;
    if (lane == 0) warp_sums[wid] = acc;
    __syncthreads();

    if (wid == 0) {
        float v = (lane < THREADS / 32) ? warp_sums[lane] : 0.0f;
        #pragma unroll
        for (int off = 4; off > 0; off >>= 1)
            v += __shfl_xor_sync(0xFFFFFFFFu, v, off);
        if (lane == 0) {
            g_partials[blockIdx.x] = v;
            __threadfence();
            unsigned int t = atomicAdd(&g_done, 1u);
            is_last = (t == (unsigned int)gridDim.x - 1u);
        }
    }
    __syncthreads();

    // ---- last block reduces the 1184 partials and stores the scalar ----
    if (is_last) {
        float v = 0.0f;
        for (int i = threadIdx.x; i < gridDim.x; i += THREADS)
            v += g_partials[i];
        #pragma unroll
        for (int off = 16; off > 0; off >>= 1)
            v += __shfl_xor_sync(0xFFFFFFFFu, v, off);
        __syncthreads();                  // warp_sums reuse
        if (lane == 0) warp_sums[wid] = v;
        __syncthreads();
        if (wid == 0) {
            float t = (lane < THREADS / 32) ? warp_sums[lane] : 0.0f;
            #pragma unroll
            for (int off = 4; off > 0; off >>= 1)
                t += __shfl_xor_sync(0xFFFFFFFFu, t, off);
            if (lane == 0) {
                out[0] = t;
                g_done = 0;               // reset for next graph replay
            }
        }
    }
}

extern "C" void kernel_launch(void* const* d_in, const int* in_sizes, int n_in,
                              void* d_out, int out_size) {
    const float* x = (const float*)d_in[0];
    const float* y = (const float*)d_in[1];
    float* out = (float*)d_out;

    const int total = in_sizes[0];    // B*N*C = 16,777,216
    const int n_slots = total / 4;    // one float4 per slot

    mloss_kernel<<<BLOCKS, THREADS>>>(x, y, out, n_slots);
}